// round 15
// baseline (speedup 1.0000x reference)
#include <cuda_runtime.h>
#include <cuda_fp16.h>
#include <math.h>
#include <stdint.h>

// B=8, M=1024, DM=768, H=12, DH=64, R=32, RFF=384, DFF=3072, RWO=384

// ---------------- scratch (device globals) ----------------
__device__ __half g_wh  [4497408];               // fp16 weights
__device__ __half g_wod [768 * 768];             // dense Uo@Vo
__device__ float  g_vb  [3ull * 12 * 64];
__device__ __half g_xh  [8192ull * 768];
__device__ float  g_t   [3ull * 8 * 1024 * 384];
__device__ __half g_qkvh[3ull * 8 * 12 * 1024 * 64];
__device__ __half g_at2h[8ull * 1024 * 768];
__device__ float  g_tmp [4ull * 8192 * 384];
__device__ float  g_x1  [8192ull * 768];
__device__ __half g_x1h [8192ull * 768];
__device__ float  g_y   [8192ull * 768];
__device__ __half g_hdnh[8192ull * 3072];

#define LOG2E 1.44269504088896340736f

__device__ __forceinline__ float gelu_exact(float v) {
    return 0.5f * v * (1.0f + erff(v * 0.70710678118654752440f));
}
__device__ __forceinline__ uint32_t h2u(float lo, float hi) {
    __half2 h = __halves2half2(__float2half_rn(lo), __float2half_rn(hi));
    return *(uint32_t*)&h;
}
__device__ __forceinline__ uint32_t ex2h2(float lo, float hi) {
    uint32_t p;
    asm("cvt.rn.f16x2.f32 %0, %2, %1;" : "=r"(p) : "f"(lo), "f"(hi));
    asm("ex2.approx.f16x2 %0, %0;" : "+r"(p));
    return p;
}
__device__ __forceinline__ float ex2f(float x) {
    float r;
    asm("ex2.approx.f32 %0, %1;" : "=f"(r) : "f"(x));
    return r;
}
__device__ __forceinline__ void mma16b(float* c, const uint32_t* a, uint32_t b0, uint32_t b1) {
    asm volatile(
        "mma.sync.aligned.m16n8k16.row.col.f32.f16.f16.f32 "
        "{%0,%1,%2,%3}, {%4,%5,%6,%7}, {%8,%9}, {%0,%1,%2,%3};"
        : "+f"(c[0]), "+f"(c[1]), "+f"(c[2]), "+f"(c[3])
        : "r"(a[0]), "r"(a[1]), "r"(a[2]), "r"(a[3]), "r"(b0), "r"(b1));
}
__device__ __forceinline__ void ldsm4(uint32_t* r, uint32_t addr) {
    asm volatile("ldmatrix.sync.aligned.m8n8.x4.shared.b16 {%0,%1,%2,%3}, [%4];"
                 : "=r"(r[0]), "=r"(r[1]), "=r"(r[2]), "=r"(r[3]) : "r"(addr));
}
__device__ __forceinline__ void ldsm4t(uint32_t* r, uint32_t addr) {
    asm volatile("ldmatrix.sync.aligned.m8n8.x4.trans.shared.b16 {%0,%1,%2,%3}, [%4];"
                 : "=r"(r[0]), "=r"(r[1]), "=r"(r[2]), "=r"(r[3]) : "r"(addr));
}
__device__ __forceinline__ uint32_t smem_u32(const void* p) {
    uint32_t a;
    asm("{ .reg .u64 t; cvta.to.shared.u64 t, %1; cvt.u32.u64 %0, t; }" : "=r"(a) : "l"(p));
    return a;
}
#define CPA16(dst, src) \
    asm volatile("cp.async.cg.shared.global [%0], [%1], 16;" ::"r"(dst), "l"(src) : "memory")
#define CPA_COMMIT() asm volatile("cp.async.commit_group;" ::: "memory")

// ================= fused flash attention =================
__global__ void __launch_bounds__(128, 2)
flash_attn(const __half* __restrict__ Qg, const __half* __restrict__ Kg,
           const __half* __restrict__ Vg, const float* __restrict__ maskg,
           __half* __restrict__ Og) {
    extern __shared__ uint32_t smu[];
    float* Ms = (float*)(smu + 18432);
    const uint32_t sbase = smem_u32(smu);

    const int bh = blockIdx.y;
    const int b = bh / 12, h = bh % 12;
    const __half* Q = Qg + (size_t)bh * 65536;
    const __half* K = Kg + (size_t)bh * 65536;
    const __half* V = Vg + (size_t)bh * 65536;
    const float* mask = maskg + b * 1024;
    __half* O = Og + (size_t)b * 1024 * 768 + h * 64;

    const int tid = threadIdx.x;
    const int wid = tid >> 5, lane = tid & 31;
    const int qr = lane >> 2, qc = lane & 3;
    const int m0row = blockIdx.x * 64 + wid * 16;

    const int nrow = (lane & 7) | ((lane >> 4) << 3);
    const int koff8 = ((lane >> 3) & 1) << 3;
    const int krow = (lane & 7) + ((lane >> 3) & 1) * 8;
    const int noff8 = ((lane >> 4) << 3);
    const uint32_t ONE2 = 0x3C003C00u;

    auto kv_load = [&](int c, int buf) {
        uint32_t dstK = sbase + buf * 36864;
        uint32_t dstV = dstK + 18432;
        const __half* Kc = K + ((size_t)(c << 7)) * 64;
        const __half* Vc = V + ((size_t)(c << 7)) * 64;
#pragma unroll
        for (int j = 0; j < 8; j++) {
            int idx = tid + (j << 7);
            int kv = idx >> 3, c4 = idx & 7;
            CPA16(dstK + kv * 144 + c4 * 16, Kc + (size_t)kv * 64 + c4 * 8);
            CPA16(dstV + kv * 144 + c4 * 16, Vc + (size_t)kv * 64 + c4 * 8);
        }
    };
#pragma unroll
    for (int j = 0; j < 2; j++) {
        int idx = tid + (j << 7);
        CPA16(smem_u32(Ms + idx * 4), mask + idx * 4);
    }
    kv_load(0, 0);
    CPA_COMMIT();
    kv_load(1, 1);
    CPA_COMMIT();

    uint32_t qf[4][4];
    {
        const float qs = 0.125f * LOG2E;
        const __half* Qr0 = Q + (size_t)(m0row + qr) * 64;
        const __half* Qr1 = Q + (size_t)(m0row + qr + 8) * 64;
#pragma unroll
        for (int kd = 0; kd < 4; kd++) {
            float2 t0 = __half22float2(*(const __half2*)(Qr0 + kd * 16 + 2 * qc));
            float2 t1 = __half22float2(*(const __half2*)(Qr1 + kd * 16 + 2 * qc));
            float2 t2 = __half22float2(*(const __half2*)(Qr0 + kd * 16 + 2 * qc + 8));
            float2 t3 = __half22float2(*(const __half2*)(Qr1 + kd * 16 + 2 * qc + 8));
            qf[kd][0] = h2u(t0.x * qs, t0.y * qs);
            qf[kd][1] = h2u(t1.x * qs, t1.y * qs);
            qf[kd][2] = h2u(t2.x * qs, t2.y * qs);
            qf[kd][3] = h2u(t3.x * qs, t3.y * qs);
        }
    }

    float oacc[8][4];
#pragma unroll
    for (int i = 0; i < 8; i++)
#pragma unroll
        for (int j = 0; j < 4; j++) oacc[i][j] = 0.0f;
    float lacc[4] = {0.0f, 0.0f, 0.0f, 0.0f};
    float mrow0 = -INFINITY, mrow1 = -INFINITY;

    for (int c = 0; c < 8; c++) {
        const int buf = c & 1;
        const uint32_t ksb = sbase + buf * 36864;
        const uint32_t vsb = ksb + 18432;
        const int kvb = c << 7;

        if (c < 7) asm volatile("cp.async.wait_group 1;" ::: "memory");
        else       asm volatile("cp.async.wait_group 0;" ::: "memory");
        __syncthreads();

        float sacc[16][4];
#pragma unroll
        for (int nt = 0; nt < 16; nt++)
            sacc[nt][0] = sacc[nt][1] = sacc[nt][2] = sacc[nt][3] = 0.0f;
#pragma unroll
        for (int ntp = 0; ntp < 8; ntp++) {
            const uint32_t rowb = ksb + (uint32_t)(ntp * 16 + nrow) * 144;
#pragma unroll
            for (int kd = 0; kd < 4; kd++) {
                uint32_t bb[4];
                ldsm4(bb, rowb + (uint32_t)(kd * 16 + koff8) * 2);
                mma16b(sacc[2 * ntp], qf[kd], bb[0], bb[1]);
                mma16b(sacc[2 * ntp + 1], qf[kd], bb[2], bb[3]);
            }
        }

        float cm0 = -INFINITY, cm1 = -INFINITY;
#pragma unroll
        for (int nt = 0; nt < 16; nt++) {
            float mk0 = Ms[kvb + nt * 8 + 2 * qc] * LOG2E;
            float mk1 = Ms[kvb + nt * 8 + 2 * qc + 1] * LOG2E;
            sacc[nt][0] += mk0; sacc[nt][1] += mk1;
            sacc[nt][2] += mk0; sacc[nt][3] += mk1;
            cm0 = fmaxf(cm0, fmaxf(sacc[nt][0], sacc[nt][1]));
            cm1 = fmaxf(cm1, fmaxf(sacc[nt][2], sacc[nt][3]));
        }
        cm0 = fmaxf(cm0, __shfl_xor_sync(0xffffffffu, cm0, 1));
        cm0 = fmaxf(cm0, __shfl_xor_sync(0xffffffffu, cm0, 2));
        cm1 = fmaxf(cm1, __shfl_xor_sync(0xffffffffu, cm1, 1));
        cm1 = fmaxf(cm1, __shfl_xor_sync(0xffffffffu, cm1, 2));
        const float mn0 = fmaxf(mrow0, cm0), mn1 = fmaxf(mrow1, cm1);
        const float al0 = ex2f(mrow0 - mn0), al1 = ex2f(mrow1 - mn1);
        mrow0 = mn0; mrow1 = mn1;
#pragma unroll
        for (int i = 0; i < 8; i++) {
            oacc[i][0] *= al0; oacc[i][1] *= al0;
            oacc[i][2] *= al1; oacc[i][3] *= al1;
        }
        lacc[0] *= al0; lacc[1] *= al0; lacc[2] *= al1; lacc[3] *= al1;

#pragma unroll
        for (int kt2 = 0; kt2 < 8; kt2++) {
            uint32_t af[4];
            af[0] = ex2h2(sacc[2 * kt2][0] - mn0, sacc[2 * kt2][1] - mn0);
            af[1] = ex2h2(sacc[2 * kt2][2] - mn1, sacc[2 * kt2][3] - mn1);
            af[2] = ex2h2(sacc[2 * kt2 + 1][0] - mn0, sacc[2 * kt2 + 1][1] - mn0);
            af[3] = ex2h2(sacc[2 * kt2 + 1][2] - mn1, sacc[2 * kt2 + 1][3] - mn1);
            mma16b(lacc, af, ONE2, ONE2);
            const uint32_t rowb = vsb + (uint32_t)(kt2 * 16 + krow) * 144;
#pragma unroll
            for (int dtp = 0; dtp < 4; dtp++) {
                uint32_t bb[4];
                ldsm4t(bb, rowb + (uint32_t)(dtp * 16 + noff8) * 2);
                mma16b(oacc[2 * dtp], af, bb[0], bb[1]);
                mma16b(oacc[2 * dtp + 1], af, bb[2], bb[3]);
            }
        }
        __syncthreads();
        if (c + 2 < 8) { kv_load(c + 2, buf); CPA_COMMIT(); }
    }

    const float il0 = 1.0f / lacc[0], il1 = 1.0f / lacc[2];
    const int r0 = m0row + qr, r1 = m0row + qr + 8;
#pragma unroll
    for (int nt2 = 0; nt2 < 8; nt2++) {
        const int col = nt2 * 8 + 2 * qc;
        *(uint32_t*)(O + (size_t)r0 * 768 + col) =
            h2u(oacc[nt2][0] * il0, oacc[nt2][1] * il0);
        *(uint32_t*)(O + (size_t)r1 * 768 + col) =
            h2u(oacc[nt2][2] * il1, oacc[nt2][3] * il1);
    }
}

// ---------------- fp16 mma GEMM; B fp16 cp.async; A fp32(reg) or fp16(cp.async) ----------------
// mode bits: 1 = gelu, 2 = fp16 output. z = (i1*D2 + i2)*D3 + i3. Strides in elements.
template <int BN, int NSUM, int AH = 0>
__global__ void __launch_bounds__(256, 2)
gemm_mma(const float* __restrict__ A, const __half* __restrict__ Bh, void* __restrict__ Cv,
         const float* __restrict__ bias, const float* __restrict__ res,
         int lda, int ldb, int ldc, int ldres, int K, float scale, int mode,
         int D2, int D3, long long sum_str,
         long long sA1, long long sA2, long long sA3,
         long long sB1, long long sB2, long long sB3,
         long long sC1, long long sC2, long long sC3,
         long long sb1, long long sb2, long long sb3) {
    constexpr int BM = 128, NT = 256, WN = BN / 4, NTILES = WN / 8, NPAIR = NTILES / 2;
    constexpr int AROW = 20;
    constexpr int BROW = BN / 2 + 4;
    constexpr int BCH = BN / 8;
    constexpr int LB = (32 * BCH) / NT > 0 ? (32 * BCH) / NT : 1;

    __shared__ uint32_t As32[2][BM * AROW];
    __shared__ uint32_t Bs32[2][32 * BROW];

    const int z = blockIdx.z;
    const int i1 = z / (D2 * D3);
    const int rem = z % (D2 * D3);
    const int i2 = rem / D3, i3 = rem % D3;
    const __half* Ah = (const __half*)A;
    if (AH) Ah += i1 * sA1 + i2 * sA2 + i3 * sA3;
    else A += i1 * sA1 + i2 * sA2 + i3 * sA3;
    Bh += i1 * sB1 + i2 * sB2 + i3 * sB3;
    const long long coff = i1 * sC1 + i2 * sC2 + i3 * sC3;
    const long long boff = i1 * sb1 + i2 * sb2 + i3 * sb3;

    const int x0 = blockIdx.x * BN, y0 = blockIdx.y * BM;
    const int tid = threadIdx.x;
    const int wid = tid >> 5, lane = tid & 31;
    const int wm0 = (wid >> 2) * 64;
    const int wn0 = (wid & 3) * WN;
    const int qr = lane >> 2, qc = lane & 3;

    const uint32_t aBase = smem_u32(As32);
    const uint32_t bBase = smem_u32(Bs32);
    const int arow_l = lane & 15, akoff = ((lane >> 4) << 3);
    const int bkrow = (lane & 7) + ((lane >> 3) & 1) * 8, bnoff = ((lane >> 4) << 3);

    float4 ra[4];

    auto cpa = [&](int k0, int buf) {
        const uint32_t bB = bBase + buf * (32 * BROW * 4);
#pragma unroll
        for (int i = 0; i < LB; i++) {
            int f = tid + i * NT;
            int k = f / BCH, c8 = f % BCH;
            CPA16(bB + (uint32_t)(k * BROW * 4 + c8 * 16),
                  Bh + (size_t)(k0 + k) * ldb + x0 + c8 * 8);
        }
        if (AH) {
            const uint32_t aB = aBase + buf * (BM * AROW * 4);
#pragma unroll
            for (int i = 0; i < 2; i++) {
                int f = tid + i * NT;
                int m = f >> 2, c4 = f & 3;
                CPA16(aB + (uint32_t)(m * AROW * 4 + c4 * 16),
                      Ah + (size_t)(y0 + m) * lda + k0 + c4 * 8);
            }
        }
    };
    auto ldgA = [&](int k0) {
        if (!AH) {
#pragma unroll
            for (int i = 0; i < 4; i++) {
                int f = tid + i * NT;
                int m = f >> 3, kq = f & 7;
                const float* ap = A + (size_t)(y0 + m) * lda + k0 + kq * 4;
                float4 v = *(const float4*)ap;
#pragma unroll
                for (int s = 1; s < NSUM; s++) {
                    float4 w = *(const float4*)(ap + (size_t)s * sum_str);
                    v.x += w.x; v.y += w.y; v.z += w.z; v.w += w.w;
                }
                ra[i] = v;
            }
        }
    };
    auto stsA = [&](int buf) {
        if (!AH) {
#pragma unroll
            for (int i = 0; i < 4; i++) {
                int f = tid + i * NT;
                int m = f >> 3, kq = f & 7;
                As32[buf][m * AROW + 2 * kq] = h2u(ra[i].x, ra[i].y);
                As32[buf][m * AROW + 2 * kq + 1] = h2u(ra[i].z, ra[i].w);
            }
        }
    };

    float acc[4][NTILES][4];
#pragma unroll
    for (int i = 0; i < 4; i++)
#pragma unroll
        for (int j = 0; j < NTILES; j++)
#pragma unroll
            for (int l = 0; l < 4; l++) acc[i][j][l] = 0.0f;

    ldgA(0);
    cpa(0, 0);
    CPA_COMMIT();
    stsA(0);
    asm volatile("cp.async.wait_group 0;" ::: "memory");
    __syncthreads();

    const int nb = K >> 5;
    for (int kb = 0; kb < nb; kb++) {
        const int cur = kb & 1;
        if (kb + 1 < nb) {
            ldgA((kb + 1) << 5);
            cpa((kb + 1) << 5, cur ^ 1);
            CPA_COMMIT();
        }
        const uint32_t aB = aBase + cur * (BM * AROW * 4);
        const uint32_t bB = bBase + cur * (32 * BROW * 4);
#pragma unroll
        for (int kk = 0; kk < 2; kk++) {
            uint32_t af[4][4], bb[NPAIR][4];
#pragma unroll
            for (int mt = 0; mt < 4; mt++)
                ldsm4(af[mt], aB + (uint32_t)(wm0 + mt * 16 + arow_l) * 80 +
                                  (uint32_t)(kk * 16 + akoff) * 2);
#pragma unroll
            for (int p = 0; p < NPAIR; p++)
                ldsm4t(bb[p], bB + (uint32_t)(kk * 16 + bkrow) * (BROW * 4) +
                                  (uint32_t)(wn0 + p * 16 + bnoff) * 2);
#pragma unroll
            for (int mt = 0; mt < 4; mt++)
#pragma unroll
                for (int p = 0; p < NPAIR; p++) {
                    mma16b(acc[mt][2 * p], af[mt], bb[p][0], bb[p][1]);
                    mma16b(acc[mt][2 * p + 1], af[mt], bb[p][2], bb[p][3]);
                }
        }
        if (kb + 1 < nb) {
            stsA(cur ^ 1);
            asm volatile("cp.async.wait_group 0;" ::: "memory");
        }
        __syncthreads();
    }

    float* Cf = (float*)Cv + coff;
    __half* Ch = (__half*)Cv + coff;
#pragma unroll
    for (int mt = 0; mt < 4; mt++) {
#pragma unroll
        for (int nt = 0; nt < NTILES; nt++) {
            const int n = x0 + wn0 + nt * 8 + qc * 2;
#pragma unroll
            for (int half_ = 0; half_ < 2; half_++) {
                const int m = y0 + wm0 + mt * 16 + qr + half_ * 8;
                float v0 = acc[mt][nt][half_ * 2 + 0] * scale;
                float v1 = acc[mt][nt][half_ * 2 + 1] * scale;
                if (bias) { v0 += bias[boff + n]; v1 += bias[boff + n + 1]; }
                if (res) {
                    v0 += res[(size_t)m * ldres + n];
                    v1 += res[(size_t)m * ldres + n + 1];
                }
                if (mode & 1) { v0 = gelu_exact(v0); v1 = gelu_exact(v1); }
                if (mode & 2) {
                    *(uint32_t*)(Ch + (size_t)m * ldc + n) = h2u(v0, v1);
                } else {
                    *(float2*)(Cf + (size_t)m * ldc + n) = make_float2(v0, v1);
                }
            }
        }
    }
}

// ---------------- packing: weights + x to fp16 ----------------
__global__ void pack_all(const float* __restrict__ Pq, const float* __restrict__ Pk,
                         const float* __restrict__ Pv,
                         const float* __restrict__ Vq, const float* __restrict__ Vk,
                         const float* __restrict__ Vv,
                         const float* __restrict__ bq, const float* __restrict__ bk,
                         const float* __restrict__ bv,
                         const float* __restrict__ Uo, const float* __restrict__ Vo,
                         const float* __restrict__ U1, const float* __restrict__ V1,
                         const float* __restrict__ U2, const float* __restrict__ V2,
                         const float* __restrict__ x,
                         __half* __restrict__ WH, float* __restrict__ VB,
                         __half* __restrict__ XH) {
    int idx = blockIdx.x * blockDim.x + threadIdx.x;
    if (idx < 884736) {
        int q = idx / (768 * 384);
        int r2 = idx % (768 * 384);
        int k = r2 / 384, n = r2 % 384;
        const float* P = (q == 0) ? Pq : ((q == 1) ? Pk : Pv);
        WH[idx] = __float2half_rn(P[((size_t)(n >> 5) * 768 + k) * 32 + (n & 31)]);
    } else if (idx < 958464) {
        int e = idx - 884736;
        int q = e / 24576, r = e % 24576;
        const float* S = (q == 0) ? Vq : ((q == 1) ? Vk : Vv);
        WH[idx] = __float2half_rn(S[r]);
    } else if (idx < 1253376) {
        WH[idx] = __float2half_rn(Uo[idx - 958464]);
    } else if (idx < 1548288) {
        WH[idx] = __float2half_rn(Vo[idx - 1253376]);
    } else if (idx < 1843200) {
        WH[idx] = __float2half_rn(U1[idx - 1548288]);
    } else if (idx < 3022848) {
        WH[idx] = __float2half_rn(V1[idx - 1843200]);
    } else if (idx < 4202496) {
        WH[idx] = __float2half_rn(U2[idx - 3022848]);
    } else if (idx < 4497408) {
        WH[idx] = __float2half_rn(V2[idx - 4202496]);
    } else if (idx < 4499712) {
        int e = idx - 4497408;
        int q = e / 768, r = e % 768;
        const float* S = (q == 0) ? bq : ((q == 1) ? bk : bv);
        VB[e] = S[r];
    } else if (idx < 4499712 + 8192 * 768) {
        int e = idx - 4499712;
        XH[e] = __float2half_rn(x[e]);
    }
}

// ---------------- LayerNorm (fp32 out + optional fp16 out) ----------------
__global__ void ln_kernel(const float* __restrict__ in, float* __restrict__ out,
                          __half* __restrict__ outh,
                          const float* __restrict__ g, const float* __restrict__ bb) {
    __shared__ float rs_[8], rss_[8];
    const float* xr = in + (size_t)blockIdx.x * 768;
    float* yr = out + (size_t)blockIdx.x * 768;
    const int tid = threadIdx.x;
    float v[3];
    float s = 0.0f, ss = 0.0f;
#pragma unroll
    for (int i = 0; i < 3; i++) {
        v[i] = xr[tid + i * 256];
        s += v[i];
        ss += v[i] * v[i];
    }
#pragma unroll
    for (int o = 16; o; o >>= 1) {
        s += __shfl_xor_sync(0xffffffffu, s, o);
        ss += __shfl_xor_sync(0xffffffffu, ss, o);
    }
    if ((tid & 31) == 0) { rs_[tid >> 5] = s; rss_[tid >> 5] = ss; }
    __syncthreads();
    s = 0.0f; ss = 0.0f;
#pragma unroll
    for (int w = 0; w < 8; w++) { s += rs_[w]; ss += rss_[w]; }
    const float mu = s * (1.0f / 768.0f);
    const float var = fmaxf(ss * (1.0f / 768.0f) - mu * mu, 0.0f);
    const float rstd = rsqrtf(var + 1e-12f);
#pragma unroll
    for (int i = 0; i < 3; i++) {
        int c = tid + i * 256;
        float o = (v[i] - mu) * rstd * g[c] + bb[c];
        yr[c] = o;
        if (outh) outh[(size_t)blockIdx.x * 768 + c] = __float2half_rn(o);
    }
}

extern "C" void kernel_launch(void* const* d_in, const int* in_sizes, int n_in,
                              void* d_out, int out_size) {
    const float* x    = (const float*)d_in[0];
    const float* mask = (const float*)d_in[1];
    const float* Pq   = (const float*)d_in[2];
    const float* Vq   = (const float*)d_in[3];
    const float* bq   = (const float*)d_in[4];
    const float* Pk   = (const float*)d_in[5];
    const float* Vk   = (const float*)d_in[6];
    const float* bk   = (const float*)d_in[7];
    const float* Pv   = (const float*)d_in[8];
    const float* Vv   = (const float*)d_in[9];
    const float* bv   = (const float*)d_in[10];
    const float* Uo   = (const float*)d_in[11];
    const float* Vo   = (const float*)d_in[12];
    const float* bo   = (const float*)d_in[13];
    const float* U1   = (const float*)d_in[14];
    const float* V1   = (const float*)d_in[15];
    const float* b1   = (const float*)d_in[16];
    const float* U2   = (const float*)d_in[17];
    const float* V2   = (const float*)d_in[18];
    const float* b2   = (const float*)d_in[19];
    const float* ln1g = (const float*)d_in[20];
    const float* ln1b = (const float*)d_in[21];
    const float* ln2g = (const float*)d_in[22];
    const float* ln2b = (const float*)d_in[23];
    float* out = (float*)d_out;

    float *vb_p, *t_p, *tmp_p, *x1_p, *y_p;
    __half *wh_p, *wod_p, *xh_p, *qkv_p, *at2_p, *x1h_p, *hdnh_p;
    cudaGetSymbolAddress((void**)&wh_p,   g_wh);
    cudaGetSymbolAddress((void**)&wod_p,  g_wod);
    cudaGetSymbolAddress((void**)&vb_p,   g_vb);
    cudaGetSymbolAddress((void**)&xh_p,   g_xh);
    cudaGetSymbolAddress((void**)&t_p,    g_t);
    cudaGetSymbolAddress((void**)&qkv_p,  g_qkvh);
    cudaGetSymbolAddress((void**)&at2_p,  g_at2h);
    cudaGetSymbolAddress((void**)&tmp_p,  g_tmp);
    cudaGetSymbolAddress((void**)&x1_p,   g_x1);
    cudaGetSymbolAddress((void**)&x1h_p,  g_x1h);
    cudaGetSymbolAddress((void**)&y_p,    g_y);
    cudaGetSymbolAddress((void**)&hdnh_p, g_hdnh);

    const long long T_QKV = 3145728, Q_QKV = 6291456, W_SZ = 294912;
    const long long PART = 3145728;
    const long long OFF_VW = 884736, OFF_UO = 958464, OFF_VO = 1253376,
                    OFF_U1 = 1548288, OFF_V1 = 1843200, OFF_U2 = 3022848,
                    OFF_V2 = 4202496;
    const int FL_SMEM = 77824;
    cudaFuncSetAttribute(flash_attn, cudaFuncAttributeMaxDynamicSharedMemorySize, FL_SMEM);

    // 0) pack weights + x -> fp16
    const int NPACK = 4499712 + 8192 * 768;
    pack_all<<<(NPACK + 255) / 256, 256>>>(Pq, Pk, Pv, Vq, Vk, Vv, bq, bk, bv,
                                           Uo, Vo, U1, V1, U2, V2, x, wh_p, vb_p, xh_p);

    // 0b) Wod = Uo @ Vo -> fp16 [768,768]
    gemm_mma<128, 1, 1><<<dim3(6, 6, 1), 256>>>(
        (const float*)(wh_p + OFF_UO), wh_p + OFF_VO, wod_p, nullptr, nullptr,
        384, 768, 768, 0, 384, 1.0f, 2, 1, 1, 0LL,
        0, 0, 0, 0, 0, 0, 0, 0, 0, 0, 0, 0);

    // 1) t = xh @ W   (z over qkv)
    gemm_mma<128, 1, 1><<<dim3(3, 64, 3), 256>>>(
        (const float*)xh_p, wh_p, t_p, nullptr, nullptr,
        768, 384, 384, 0, 768, 1.0f, 0, 1, 1, 0LL,
        0LL, 0LL, 0LL, W_SZ, 0LL, 0LL, T_QKV, 0LL, 0LL, 0LL, 0LL, 0LL);

    // 2) Q/K/V = t @ Vqkv + b -> fp16. z=(q,b,h), K=32
    gemm_mma<64, 1><<<dim3(1, 8, 288), 256>>>(
        t_p, wh_p + OFF_VW, qkv_p, vb_p, nullptr,
        384, 64, 64, 0, 32, 1.0f, 2, 8, 12, 0LL,
        T_QKV, 393216LL, 32LL,
        24576LL, 0LL, 2048LL,
        Q_QKV, 786432LL, 65536LL,
        768LL, 0LL, 64LL);

    // 3) fused attention -> at2 (fp16)
    flash_attn<<<dim3(16, 96), 128, FL_SMEM>>>(
        qkv_p, qkv_p + Q_QKV, qkv_p + 2 * Q_QKV, mask, at2_p);

    // 4) x1pre = attn @ Wod + bo + x   (fused Uo@Vo)
    gemm_mma<128, 1, 1><<<dim3(6, 64, 1), 256>>>(
        (const float*)at2_p, wod_p, y_p, bo, x,
        768, 768, 768, 768, 768, 1.0f, 0, 1, 1, 0LL,
        0, 0, 0, 0, 0, 0, 0, 0, 0, 0, 0, 0);

    // 5) LN1 -> x1 (fp32) + x1h (fp16)
    ln_kernel<<<8192, 256>>>(y_p, x1_p, x1h_p, ln1g, ln1b);

    // 6) mid partials = x1h @ U1  (split-K x2)
    gemm_mma<128, 1, 1><<<dim3(3, 64, 2), 256>>>(
        (const float*)x1h_p, wh_p + OFF_U1, tmp_p, nullptr, nullptr,
        768, 384, 384, 0, 384, 1.0f, 0, 1, 2, 0LL,
        0LL, 0LL, 384LL, 0LL, 0LL, 147456LL, 0LL, 0LL, PART, 0, 0, 0);

    // 7) hdn = gelu(sum(mid) @ V1 + b1) -> fp16
    gemm_mma<128, 2><<<dim3(24, 64, 1), 256>>>(
        tmp_p, wh_p + OFF_V1, hdnh_p, b1, nullptr,
        384, 3072, 3072, 0, 384, 1.0f, 3, 1, 1, PART,
        0, 0, 0, 0, 0, 0, 0, 0, 0, 0, 0, 0);

    // 8) h2 partials = hdn(fp16) @ U2  (split-K x4)
    gemm_mma<128, 1, 1><<<dim3(3, 64, 4), 256>>>(
        (const float*)hdnh_p, wh_p + OFF_U2, tmp_p, nullptr, nullptr,
        3072, 384, 384, 0, 768, 1.0f, 0, 1, 4, 0LL,
        0LL, 0LL, 768LL, 0LL, 0LL, 294912LL, 0LL, 0LL, PART, 0, 0, 0);

    // 9) ypre = sum(h2) @ V2 + b2 + x1
    gemm_mma<128, 4><<<dim3(6, 64, 1), 256>>>(
        tmp_p, wh_p + OFF_V2, y_p, b2, x1_p,
        384, 768, 768, 768, 384, 1.0f, 0, 1, 1, PART,
        0, 0, 0, 0, 0, 0, 0, 0, 0, 0, 0, 0);

    // 10) LN2 -> out
    ln_kernel<<<8192, 256>>>(y_p, out, nullptr, ln2g, ln2b);
}

// round 16
// speedup vs baseline: 1.0413x; 1.0413x over previous
#include <cuda_runtime.h>
#include <cuda_fp16.h>
#include <math.h>
#include <stdint.h>

// B=8, M=1024, DM=768, H=12, DH=64, R=32, RFF=384, DFF=3072, RWO=384

// ---------------- scratch (device globals) ----------------
__device__ __half g_wh  [4497408];               // all fp16 weights
__device__ __half g_wod [768 * 768];             // dense Uo@Vo (fp16)
__device__ float  g_vb  [3ull * 12 * 64];
__device__ float  g_t   [3ull * 8 * 1024 * 384];
__device__ __half g_qkvh[3ull * 8 * 12 * 1024 * 64];
__device__ __half g_at2h[8ull * 1024 * 768];
__device__ float  g_tmp [4ull * 8192 * 384];
__device__ float  g_x1  [8192ull * 768];
__device__ float  g_y   [8192ull * 768];
__device__ __half g_hdnh[8192ull * 3072];

#define LOG2E 1.44269504088896340736f

__device__ __forceinline__ float gelu_exact(float v) {
    return 0.5f * v * (1.0f + erff(v * 0.70710678118654752440f));
}
__device__ __forceinline__ uint32_t h2u(float lo, float hi) {
    __half2 h = __halves2half2(__float2half_rn(lo), __float2half_rn(hi));
    return *(uint32_t*)&h;
}
__device__ __forceinline__ uint32_t ex2h2(float lo, float hi) {
    uint32_t p;
    asm("cvt.rn.f16x2.f32 %0, %2, %1;" : "=r"(p) : "f"(lo), "f"(hi));
    asm("ex2.approx.f16x2 %0, %0;" : "+r"(p));
    return p;
}
__device__ __forceinline__ float ex2f(float x) {
    float r;
    asm("ex2.approx.f32 %0, %1;" : "=f"(r) : "f"(x));
    return r;
}
__device__ __forceinline__ void mma16b(float* c, const uint32_t* a, uint32_t b0, uint32_t b1) {
    asm volatile(
        "mma.sync.aligned.m16n8k16.row.col.f32.f16.f16.f32 "
        "{%0,%1,%2,%3}, {%4,%5,%6,%7}, {%8,%9}, {%0,%1,%2,%3};"
        : "+f"(c[0]), "+f"(c[1]), "+f"(c[2]), "+f"(c[3])
        : "r"(a[0]), "r"(a[1]), "r"(a[2]), "r"(a[3]), "r"(b0), "r"(b1));
}
__device__ __forceinline__ void ldsm4(uint32_t* r, uint32_t addr) {
    asm volatile("ldmatrix.sync.aligned.m8n8.x4.shared.b16 {%0,%1,%2,%3}, [%4];"
                 : "=r"(r[0]), "=r"(r[1]), "=r"(r[2]), "=r"(r[3]) : "r"(addr));
}
__device__ __forceinline__ void ldsm4t(uint32_t* r, uint32_t addr) {
    asm volatile("ldmatrix.sync.aligned.m8n8.x4.trans.shared.b16 {%0,%1,%2,%3}, [%4];"
                 : "=r"(r[0]), "=r"(r[1]), "=r"(r[2]), "=r"(r[3]) : "r"(addr));
}
__device__ __forceinline__ uint32_t smem_u32(const void* p) {
    uint32_t a;
    asm("{ .reg .u64 t; cvta.to.shared.u64 t, %1; cvt.u32.u64 %0, t; }" : "=r"(a) : "l"(p));
    return a;
}
#define CPA16(dst, src) \
    asm volatile("cp.async.cg.shared.global [%0], [%1], 16;" ::"r"(dst), "l"(src) : "memory")
#define CPA_COMMIT() asm volatile("cp.async.commit_group;" ::: "memory")

// ================= fused flash attention (log2 softmax, fp16 output) =================
__global__ void __launch_bounds__(128, 2)
flash_attn(const __half* __restrict__ Qg, const __half* __restrict__ Kg,
           const __half* __restrict__ Vg, const float* __restrict__ maskg,
           __half* __restrict__ Og) {
    extern __shared__ uint32_t smu[];
    float* Ms = (float*)(smu + 18432);
    const uint32_t sbase = smem_u32(smu);

    const int bh = blockIdx.y;
    const int b = bh / 12, h = bh % 12;
    const __half* Q = Qg + (size_t)bh * 65536;
    const __half* K = Kg + (size_t)bh * 65536;
    const __half* V = Vg + (size_t)bh * 65536;
    const float* mask = maskg + b * 1024;
    __half* O = Og + (size_t)b * 1024 * 768 + h * 64;

    const int tid = threadIdx.x;
    const int wid = tid >> 5, lane = tid & 31;
    const int qr = lane >> 2, qc = lane & 3;
    const int m0row = blockIdx.x * 64 + wid * 16;

    const int nrow = (lane & 7) | ((lane >> 4) << 3);
    const int koff8 = ((lane >> 3) & 1) << 3;
    const int krow = (lane & 7) + ((lane >> 3) & 1) * 8;
    const int noff8 = ((lane >> 4) << 3);
    const uint32_t ONE2 = 0x3C003C00u;

    auto kv_load = [&](int c, int buf) {
        uint32_t dstK = sbase + buf * 36864;
        uint32_t dstV = dstK + 18432;
        const __half* Kc = K + ((size_t)(c << 7)) * 64;
        const __half* Vc = V + ((size_t)(c << 7)) * 64;
#pragma unroll
        for (int j = 0; j < 8; j++) {
            int idx = tid + (j << 7);
            int kv = idx >> 3, c4 = idx & 7;
            CPA16(dstK + kv * 144 + c4 * 16, Kc + (size_t)kv * 64 + c4 * 8);
            CPA16(dstV + kv * 144 + c4 * 16, Vc + (size_t)kv * 64 + c4 * 8);
        }
    };
#pragma unroll
    for (int j = 0; j < 2; j++) {
        int idx = tid + (j << 7);
        CPA16(smem_u32(Ms + idx * 4), mask + idx * 4);
    }
    kv_load(0, 0);
    CPA_COMMIT();
    kv_load(1, 1);
    CPA_COMMIT();

    uint32_t qf[4][4];
    {
        const float qs = 0.125f * LOG2E;
        const __half* Qr0 = Q + (size_t)(m0row + qr) * 64;
        const __half* Qr1 = Q + (size_t)(m0row + qr + 8) * 64;
#pragma unroll
        for (int kd = 0; kd < 4; kd++) {
            float2 t0 = __half22float2(*(const __half2*)(Qr0 + kd * 16 + 2 * qc));
            float2 t1 = __half22float2(*(const __half2*)(Qr1 + kd * 16 + 2 * qc));
            float2 t2 = __half22float2(*(const __half2*)(Qr0 + kd * 16 + 2 * qc + 8));
            float2 t3 = __half22float2(*(const __half2*)(Qr1 + kd * 16 + 2 * qc + 8));
            qf[kd][0] = h2u(t0.x * qs, t0.y * qs);
            qf[kd][1] = h2u(t1.x * qs, t1.y * qs);
            qf[kd][2] = h2u(t2.x * qs, t2.y * qs);
            qf[kd][3] = h2u(t3.x * qs, t3.y * qs);
        }
    }

    float oacc[8][4];
#pragma unroll
    for (int i = 0; i < 8; i++)
#pragma unroll
        for (int j = 0; j < 4; j++) oacc[i][j] = 0.0f;
    float lacc[4] = {0.0f, 0.0f, 0.0f, 0.0f};
    float mrow0 = -INFINITY, mrow1 = -INFINITY;

    for (int c = 0; c < 8; c++) {
        const int buf = c & 1;
        const uint32_t ksb = sbase + buf * 36864;
        const uint32_t vsb = ksb + 18432;
        const int kvb = c << 7;

        if (c < 7) asm volatile("cp.async.wait_group 1;" ::: "memory");
        else       asm volatile("cp.async.wait_group 0;" ::: "memory");
        __syncthreads();

        float sacc[16][4];
#pragma unroll
        for (int nt = 0; nt < 16; nt++)
            sacc[nt][0] = sacc[nt][1] = sacc[nt][2] = sacc[nt][3] = 0.0f;
#pragma unroll
        for (int ntp = 0; ntp < 8; ntp++) {
            const uint32_t rowb = ksb + (uint32_t)(ntp * 16 + nrow) * 144;
#pragma unroll
            for (int kd = 0; kd < 4; kd++) {
                uint32_t bb[4];
                ldsm4(bb, rowb + (uint32_t)(kd * 16 + koff8) * 2);
                mma16b(sacc[2 * ntp], qf[kd], bb[0], bb[1]);
                mma16b(sacc[2 * ntp + 1], qf[kd], bb[2], bb[3]);
            }
        }

        float cm0 = -INFINITY, cm1 = -INFINITY;
#pragma unroll
        for (int nt = 0; nt < 16; nt++) {
            float mk0 = Ms[kvb + nt * 8 + 2 * qc] * LOG2E;
            float mk1 = Ms[kvb + nt * 8 + 2 * qc + 1] * LOG2E;
            sacc[nt][0] += mk0; sacc[nt][1] += mk1;
            sacc[nt][2] += mk0; sacc[nt][3] += mk1;
            cm0 = fmaxf(cm0, fmaxf(sacc[nt][0], sacc[nt][1]));
            cm1 = fmaxf(cm1, fmaxf(sacc[nt][2], sacc[nt][3]));
        }
        cm0 = fmaxf(cm0, __shfl_xor_sync(0xffffffffu, cm0, 1));
        cm0 = fmaxf(cm0, __shfl_xor_sync(0xffffffffu, cm0, 2));
        cm1 = fmaxf(cm1, __shfl_xor_sync(0xffffffffu, cm1, 1));
        cm1 = fmaxf(cm1, __shfl_xor_sync(0xffffffffu, cm1, 2));
        const float mn0 = fmaxf(mrow0, cm0), mn1 = fmaxf(mrow1, cm1);
        const float al0 = ex2f(mrow0 - mn0), al1 = ex2f(mrow1 - mn1);
        mrow0 = mn0; mrow1 = mn1;
#pragma unroll
        for (int i = 0; i < 8; i++) {
            oacc[i][0] *= al0; oacc[i][1] *= al0;
            oacc[i][2] *= al1; oacc[i][3] *= al1;
        }
        lacc[0] *= al0; lacc[1] *= al0; lacc[2] *= al1; lacc[3] *= al1;

#pragma unroll
        for (int kt2 = 0; kt2 < 8; kt2++) {
            uint32_t af[4];
            af[0] = ex2h2(sacc[2 * kt2][0] - mn0, sacc[2 * kt2][1] - mn0);
            af[1] = ex2h2(sacc[2 * kt2][2] - mn1, sacc[2 * kt2][3] - mn1);
            af[2] = ex2h2(sacc[2 * kt2 + 1][0] - mn0, sacc[2 * kt2 + 1][1] - mn0);
            af[3] = ex2h2(sacc[2 * kt2 + 1][2] - mn1, sacc[2 * kt2 + 1][3] - mn1);
            mma16b(lacc, af, ONE2, ONE2);
            const uint32_t rowb = vsb + (uint32_t)(kt2 * 16 + krow) * 144;
#pragma unroll
            for (int dtp = 0; dtp < 4; dtp++) {
                uint32_t bb[4];
                ldsm4t(bb, rowb + (uint32_t)(dtp * 16 + noff8) * 2);
                mma16b(oacc[2 * dtp], af, bb[0], bb[1]);
                mma16b(oacc[2 * dtp + 1], af, bb[2], bb[3]);
            }
        }
        __syncthreads();
        if (c + 2 < 8) { kv_load(c + 2, buf); CPA_COMMIT(); }
    }

    const float il0 = 1.0f / lacc[0], il1 = 1.0f / lacc[2];
    const int r0 = m0row + qr, r1 = m0row + qr + 8;
#pragma unroll
    for (int nt2 = 0; nt2 < 8; nt2++) {
        const int col = nt2 * 8 + 2 * qc;
        *(uint32_t*)(O + (size_t)r0 * 768 + col) =
            h2u(oacc[nt2][0] * il0, oacc[nt2][1] * il0);
        *(uint32_t*)(O + (size_t)r1 * 768 + col) =
            h2u(oacc[nt2][2] * il1, oacc[nt2][3] * il1);
    }
}

// ---------------- fp16 mma GEMM; B fp16 cp.async; A fp32(reg) or fp16(cp.async) ----------------
// mode bits: 1 = gelu, 2 = fp16 output. z = (i1*D2 + i2)*D3 + i3. Strides in elements.
template <int BN, int NSUM, int AH = 0>
__global__ void __launch_bounds__(256, 2)
gemm_mma(const float* __restrict__ A, const __half* __restrict__ Bh, void* __restrict__ Cv,
         const float* __restrict__ bias, const float* __restrict__ res,
         int lda, int ldb, int ldc, int ldres, int K, float scale, int mode,
         int D2, int D3, long long sum_str,
         long long sA1, long long sA2, long long sA3,
         long long sB1, long long sB2, long long sB3,
         long long sC1, long long sC2, long long sC3,
         long long sb1, long long sb2, long long sb3) {
    constexpr int BM = 128, NT = 256, WN = BN / 4, NTILES = WN / 8, NPAIR = NTILES / 2;
    constexpr int AROW = 20;
    constexpr int BROW = BN / 2 + 4;
    constexpr int BCH = BN / 8;
    constexpr int LB = (32 * BCH) / NT > 0 ? (32 * BCH) / NT : 1;

    __shared__ uint32_t As32[2][BM * AROW];
    __shared__ uint32_t Bs32[2][32 * BROW];

    const int z = blockIdx.z;
    const int i1 = z / (D2 * D3);
    const int rem = z % (D2 * D3);
    const int i2 = rem / D3, i3 = rem % D3;
    const __half* Ah = (const __half*)A;
    if (AH) Ah += i1 * sA1 + i2 * sA2 + i3 * sA3;
    else A += i1 * sA1 + i2 * sA2 + i3 * sA3;
    Bh += i1 * sB1 + i2 * sB2 + i3 * sB3;
    const long long coff = i1 * sC1 + i2 * sC2 + i3 * sC3;
    const long long boff = i1 * sb1 + i2 * sb2 + i3 * sb3;

    const int x0 = blockIdx.x * BN, y0 = blockIdx.y * BM;
    const int tid = threadIdx.x;
    const int wid = tid >> 5, lane = tid & 31;
    const int wm0 = (wid >> 2) * 64;
    const int wn0 = (wid & 3) * WN;
    const int qr = lane >> 2, qc = lane & 3;

    const uint32_t aBase = smem_u32(As32);
    const uint32_t bBase = smem_u32(Bs32);
    const int arow_l = lane & 15, akoff = ((lane >> 4) << 3);
    const int bkrow = (lane & 7) + ((lane >> 3) & 1) * 8, bnoff = ((lane >> 4) << 3);

    float4 ra[4];

    auto cpa = [&](int k0, int buf) {
        const uint32_t bB = bBase + buf * (32 * BROW * 4);
#pragma unroll
        for (int i = 0; i < LB; i++) {
            int f = tid + i * NT;
            int k = f / BCH, c8 = f % BCH;
            CPA16(bB + (uint32_t)(k * BROW * 4 + c8 * 16),
                  Bh + (size_t)(k0 + k) * ldb + x0 + c8 * 8);
        }
        if (AH) {
            const uint32_t aB = aBase + buf * (BM * AROW * 4);
#pragma unroll
            for (int i = 0; i < 2; i++) {
                int f = tid + i * NT;
                int m = f >> 2, c4 = f & 3;
                CPA16(aB + (uint32_t)(m * AROW * 4 + c4 * 16),
                      Ah + (size_t)(y0 + m) * lda + k0 + c4 * 8);
            }
        }
    };
    auto ldgA = [&](int k0) {
        if (!AH) {
#pragma unroll
            for (int i = 0; i < 4; i++) {
                int f = tid + i * NT;
                int m = f >> 3, kq = f & 7;
                const float* ap = A + (size_t)(y0 + m) * lda + k0 + kq * 4;
                float4 v = *(const float4*)ap;
#pragma unroll
                for (int s = 1; s < NSUM; s++) {
                    float4 w = *(const float4*)(ap + (size_t)s * sum_str);
                    v.x += w.x; v.y += w.y; v.z += w.z; v.w += w.w;
                }
                ra[i] = v;
            }
        }
    };
    auto stsA = [&](int buf) {
        if (!AH) {
#pragma unroll
            for (int i = 0; i < 4; i++) {
                int f = tid + i * NT;
                int m = f >> 3, kq = f & 7;
                As32[buf][m * AROW + 2 * kq] = h2u(ra[i].x, ra[i].y);
                As32[buf][m * AROW + 2 * kq + 1] = h2u(ra[i].z, ra[i].w);
            }
        }
    };

    float acc[4][NTILES][4];
#pragma unroll
    for (int i = 0; i < 4; i++)
#pragma unroll
        for (int j = 0; j < NTILES; j++)
#pragma unroll
            for (int l = 0; l < 4; l++) acc[i][j][l] = 0.0f;

    ldgA(0);
    cpa(0, 0);
    CPA_COMMIT();
    stsA(0);
    asm volatile("cp.async.wait_group 0;" ::: "memory");
    __syncthreads();

    const int nb = K >> 5;
    for (int kb = 0; kb < nb; kb++) {
        const int cur = kb & 1;
        if (kb + 1 < nb) {
            ldgA((kb + 1) << 5);
            cpa((kb + 1) << 5, cur ^ 1);
            CPA_COMMIT();
        }
        const uint32_t aB = aBase + cur * (BM * AROW * 4);
        const uint32_t bB = bBase + cur * (32 * BROW * 4);
#pragma unroll
        for (int kk = 0; kk < 2; kk++) {
            uint32_t af[4][4], bb[NPAIR][4];
#pragma unroll
            for (int mt = 0; mt < 4; mt++)
                ldsm4(af[mt], aB + (uint32_t)(wm0 + mt * 16 + arow_l) * 80 +
                                  (uint32_t)(kk * 16 + akoff) * 2);
#pragma unroll
            for (int p = 0; p < NPAIR; p++)
                ldsm4t(bb[p], bB + (uint32_t)(kk * 16 + bkrow) * (BROW * 4) +
                                  (uint32_t)(wn0 + p * 16 + bnoff) * 2);
#pragma unroll
            for (int mt = 0; mt < 4; mt++)
#pragma unroll
                for (int p = 0; p < NPAIR; p++) {
                    mma16b(acc[mt][2 * p], af[mt], bb[p][0], bb[p][1]);
                    mma16b(acc[mt][2 * p + 1], af[mt], bb[p][2], bb[p][3]);
                }
        }
        if (kb + 1 < nb) {
            stsA(cur ^ 1);
            asm volatile("cp.async.wait_group 0;" ::: "memory");
        }
        __syncthreads();
    }

    float* Cf = (float*)Cv + coff;
    __half* Ch = (__half*)Cv + coff;
#pragma unroll
    for (int mt = 0; mt < 4; mt++) {
#pragma unroll
        for (int nt = 0; nt < NTILES; nt++) {
            const int n = x0 + wn0 + nt * 8 + qc * 2;
#pragma unroll
            for (int half_ = 0; half_ < 2; half_++) {
                const int m = y0 + wm0 + mt * 16 + qr + half_ * 8;
                float v0 = acc[mt][nt][half_ * 2 + 0] * scale;
                float v1 = acc[mt][nt][half_ * 2 + 1] * scale;
                if (bias) { v0 += bias[boff + n]; v1 += bias[boff + n + 1]; }
                if (res) {
                    v0 += res[(size_t)m * ldres + n];
                    v1 += res[(size_t)m * ldres + n + 1];
                }
                if (mode & 1) { v0 = gelu_exact(v0); v1 = gelu_exact(v1); }
                if (mode & 2) {
                    *(uint32_t*)(Ch + (size_t)m * ldc + n) = h2u(v0, v1);
                } else {
                    *(float2*)(Cf + (size_t)m * ldc + n) = make_float2(v0, v1);
                }
            }
        }
    }
}

// ---------------- packing: all weights to fp16 ----------------
__global__ void pack_all(const float* __restrict__ Pq, const float* __restrict__ Pk,
                         const float* __restrict__ Pv,
                         const float* __restrict__ Vq, const float* __restrict__ Vk,
                         const float* __restrict__ Vv,
                         const float* __restrict__ bq, const float* __restrict__ bk,
                         const float* __restrict__ bv,
                         const float* __restrict__ Uo, const float* __restrict__ Vo,
                         const float* __restrict__ U1, const float* __restrict__ V1,
                         const float* __restrict__ U2, const float* __restrict__ V2,
                         __half* __restrict__ WH, float* __restrict__ VB) {
    int idx = blockIdx.x * blockDim.x + threadIdx.x;
    if (idx < 884736) {
        int q = idx / (768 * 384);
        int r2 = idx % (768 * 384);
        int k = r2 / 384, n = r2 % 384;
        const float* P = (q == 0) ? Pq : ((q == 1) ? Pk : Pv);
        WH[idx] = __float2half_rn(P[((size_t)(n >> 5) * 768 + k) * 32 + (n & 31)]);
    } else if (idx < 958464) {
        int e = idx - 884736;
        int q = e / 24576, r = e % 24576;
        const float* S = (q == 0) ? Vq : ((q == 1) ? Vk : Vv);
        WH[idx] = __float2half_rn(S[r]);
    } else if (idx < 1253376) {
        WH[idx] = __float2half_rn(Uo[idx - 958464]);
    } else if (idx < 1548288) {
        WH[idx] = __float2half_rn(Vo[idx - 1253376]);
    } else if (idx < 1843200) {
        WH[idx] = __float2half_rn(U1[idx - 1548288]);
    } else if (idx < 3022848) {
        WH[idx] = __float2half_rn(V1[idx - 1843200]);
    } else if (idx < 4202496) {
        WH[idx] = __float2half_rn(U2[idx - 3022848]);
    } else if (idx < 4497408) {
        WH[idx] = __float2half_rn(V2[idx - 4202496]);
    } else if (idx < 4497408 + 2304) {
        int e = idx - 4497408;
        int q = e / 768, r = e % 768;
        const float* S = (q == 0) ? bq : ((q == 1) ? bk : bv);
        VB[e] = S[r];
    }
}

// ---------------- LayerNorm (single pass) ----------------
__global__ void ln_kernel(const float* __restrict__ in, float* __restrict__ out,
                          const float* __restrict__ g, const float* __restrict__ bb) {
    __shared__ float rs_[8], rss_[8];
    const float* xr = in + (size_t)blockIdx.x * 768;
    float* yr = out + (size_t)blockIdx.x * 768;
    const int tid = threadIdx.x;
    float v[3];
    float s = 0.0f, ss = 0.0f;
#pragma unroll
    for (int i = 0; i < 3; i++) {
        v[i] = xr[tid + i * 256];
        s += v[i];
        ss += v[i] * v[i];
    }
#pragma unroll
    for (int o = 16; o; o >>= 1) {
        s += __shfl_xor_sync(0xffffffffu, s, o);
        ss += __shfl_xor_sync(0xffffffffu, ss, o);
    }
    if ((tid & 31) == 0) { rs_[tid >> 5] = s; rss_[tid >> 5] = ss; }
    __syncthreads();
    s = 0.0f; ss = 0.0f;
#pragma unroll
    for (int w = 0; w < 8; w++) { s += rs_[w]; ss += rss_[w]; }
    const float mu = s * (1.0f / 768.0f);
    const float var = fmaxf(ss * (1.0f / 768.0f) - mu * mu, 0.0f);
    const float rstd = rsqrtf(var + 1e-12f);
#pragma unroll
    for (int i = 0; i < 3; i++) {
        int c = tid + i * 256;
        yr[c] = (v[i] - mu) * rstd * g[c] + bb[c];
    }
}

extern "C" void kernel_launch(void* const* d_in, const int* in_sizes, int n_in,
                              void* d_out, int out_size) {
    const float* x    = (const float*)d_in[0];
    const float* mask = (const float*)d_in[1];
    const float* Pq   = (const float*)d_in[2];
    const float* Vq   = (const float*)d_in[3];
    const float* bq   = (const float*)d_in[4];
    const float* Pk   = (const float*)d_in[5];
    const float* Vk   = (const float*)d_in[6];
    const float* bk   = (const float*)d_in[7];
    const float* Pv   = (const float*)d_in[8];
    const float* Vv   = (const float*)d_in[9];
    const float* bv   = (const float*)d_in[10];
    const float* Uo   = (const float*)d_in[11];
    const float* Vo   = (const float*)d_in[12];
    const float* bo   = (const float*)d_in[13];
    const float* U1   = (const float*)d_in[14];
    const float* V1   = (const float*)d_in[15];
    const float* b1   = (const float*)d_in[16];
    const float* U2   = (const float*)d_in[17];
    const float* V2   = (const float*)d_in[18];
    const float* b2   = (const float*)d_in[19];
    const float* ln1g = (const float*)d_in[20];
    const float* ln1b = (const float*)d_in[21];
    const float* ln2g = (const float*)d_in[22];
    const float* ln2b = (const float*)d_in[23];
    float* out = (float*)d_out;

    float *vb_p, *t_p, *tmp_p, *x1_p, *y_p;
    __half *wh_p, *wod_p, *qkv_p, *at2_p, *hdnh_p;
    cudaGetSymbolAddress((void**)&wh_p,   g_wh);
    cudaGetSymbolAddress((void**)&wod_p,  g_wod);
    cudaGetSymbolAddress((void**)&vb_p,   g_vb);
    cudaGetSymbolAddress((void**)&t_p,    g_t);
    cudaGetSymbolAddress((void**)&qkv_p,  g_qkvh);
    cudaGetSymbolAddress((void**)&at2_p,  g_at2h);
    cudaGetSymbolAddress((void**)&tmp_p,  g_tmp);
    cudaGetSymbolAddress((void**)&x1_p,   g_x1);
    cudaGetSymbolAddress((void**)&y_p,    g_y);
    cudaGetSymbolAddress((void**)&hdnh_p, g_hdnh);

    const long long T_QKV = 3145728, Q_QKV = 6291456, W_SZ = 294912;
    const long long PART = 3145728;
    const long long OFF_VW = 884736, OFF_UO = 958464, OFF_VO = 1253376,
                    OFF_U1 = 1548288, OFF_V1 = 1843200, OFF_U2 = 3022848,
                    OFF_V2 = 4202496;
    const int FL_SMEM = 77824;
    cudaFuncSetAttribute(flash_attn, cudaFuncAttributeMaxDynamicSharedMemorySize, FL_SMEM);

    // 0) pack all weights to fp16
    const int NPACK = 4497408 + 2304;
    pack_all<<<(NPACK + 255) / 256, 256>>>(Pq, Pk, Pv, Vq, Vk, Vv, bq, bk, bv,
                                           Uo, Vo, U1, V1, U2, V2, wh_p, vb_p);

    // 0b) Wod = Uo @ Vo -> fp16 [768,768]  (runs while nothing depends on it yet)
    gemm_mma<128, 1, 1><<<dim3(6, 6, 1), 256>>>(
        (const float*)(wh_p + OFF_UO), wh_p + OFF_VO, wod_p, nullptr, nullptr,
        384, 768, 768, 0, 384, 1.0f, 2, 1, 1, 0LL,
        0, 0, 0, 0, 0, 0, 0, 0, 0, 0, 0, 0);

    // 1) t = x @ W   (fp32 A path; z over qkv)
    gemm_mma<128, 1><<<dim3(3, 64, 3), 256>>>(
        x, wh_p, t_p, nullptr, nullptr,
        768, 384, 384, 0, 768, 1.0f, 0, 1, 1, 0LL,
        0LL, 0LL, 0LL, W_SZ, 0LL, 0LL, T_QKV, 0LL, 0LL, 0LL, 0LL, 0LL);

    // 2) Q/K/V = t @ Vqkv + b -> fp16. z=(q,b,h), K=32
    gemm_mma<64, 1><<<dim3(1, 8, 288), 256>>>(
        t_p, wh_p + OFF_VW, qkv_p, vb_p, nullptr,
        384, 64, 64, 0, 32, 1.0f, 2, 8, 12, 0LL,
        T_QKV, 393216LL, 32LL,
        24576LL, 0LL, 2048LL,
        Q_QKV, 786432LL, 65536LL,
        768LL, 0LL, 64LL);

    // 3) fused attention -> at2 (fp16)
    flash_attn<<<dim3(16, 96), 128, FL_SMEM>>>(
        qkv_p, qkv_p + Q_QKV, qkv_p + 2 * Q_QKV, mask, at2_p);

    // 4) x1pre = attn @ Wod + bo + x   (fused Uo@Vo, K=768, fp16 A)
    gemm_mma<128, 1, 1><<<dim3(6, 64, 1), 256>>>(
        (const float*)at2_p, wod_p, y_p, bo, x,
        768, 768, 768, 768, 768, 1.0f, 0, 1, 1, 0LL,
        0, 0, 0, 0, 0, 0, 0, 0, 0, 0, 0, 0);

    // 5) LN1
    ln_kernel<<<8192, 256>>>(y_p, x1_p, ln1g, ln1b);

    // 6) mid partials = x1 @ U1  (split-K x2, fp32 A path)
    gemm_mma<128, 1><<<dim3(3, 64, 2), 256>>>(
        x1_p, wh_p + OFF_U1, tmp_p, nullptr, nullptr,
        768, 384, 384, 0, 384, 1.0f, 0, 1, 2, 0LL,
        0LL, 0LL, 384LL, 0LL, 0LL, 147456LL, 0LL, 0LL, PART, 0, 0, 0);

    // 7) hdn = gelu(sum(mid) @ V1 + b1) -> fp16
    gemm_mma<128, 2><<<dim3(24, 64, 1), 256>>>(
        tmp_p, wh_p + OFF_V1, hdnh_p, b1, nullptr,
        384, 3072, 3072, 0, 384, 1.0f, 3, 1, 1, PART,
        0, 0, 0, 0, 0, 0, 0, 0, 0, 0, 0, 0);

    // 8) h2 partials = hdn(fp16) @ U2  (split-K x4)
    gemm_mma<128, 1, 1><<<dim3(3, 64, 4), 256>>>(
        (const float*)hdnh_p, wh_p + OFF_U2, tmp_p, nullptr, nullptr,
        3072, 384, 384, 0, 768, 1.0f, 0, 1, 4, 0LL,
        0LL, 0LL, 768LL, 0LL, 0LL, 294912LL, 0LL, 0LL, PART, 0, 0, 0);

    // 9) ypre = sum(h2) @ V2 + b2 + x1
    gemm_mma<128, 4><<<dim3(6, 64, 1), 256>>>(
        tmp_p, wh_p + OFF_V2, y_p, b2, x1_p,
        384, 768, 768, 768, 384, 1.0f, 0, 1, 1, PART,
        0, 0, 0, 0, 0, 0, 0, 0, 0, 0, 0, 0);

    // 10) LN2 -> out
    ln_kernel<<<8192, 256>>>(y_p, out, ln2g, ln2b);
}

// round 17
// speedup vs baseline: 1.0413x; 1.0001x over previous
#include <cuda_runtime.h>
#include <cuda_fp16.h>
#include <math.h>
#include <stdint.h>

// B=8, M=1024, DM=768, H=12, DH=64, R=32, RFF=384, DFF=3072, RWO=384

// ---------------- scratch (device globals) ----------------
__device__ __half g_wh  [4497408];               // all fp16 weights
__device__ __half g_wod [768 * 768];             // dense Uo@Vo (fp16)
__device__ float  g_vb  [3ull * 12 * 64];
__device__ __half g_th  [3ull * 8 * 1024 * 384]; // fp16 t
__device__ __half g_qkvh[3ull * 8 * 12 * 1024 * 64];
__device__ __half g_at2h[8ull * 1024 * 768];
__device__ float  g_tmp [4ull * 8192 * 384];
__device__ float  g_x1  [8192ull * 768];
__device__ float  g_y   [8192ull * 768];
__device__ __half g_hdnh[8192ull * 3072];

#define LOG2E 1.44269504088896340736f

__device__ __forceinline__ float gelu_exact(float v) {
    return 0.5f * v * (1.0f + erff(v * 0.70710678118654752440f));
}
__device__ __forceinline__ uint32_t h2u(float lo, float hi) {
    __half2 h = __halves2half2(__float2half_rn(lo), __float2half_rn(hi));
    return *(uint32_t*)&h;
}
__device__ __forceinline__ uint32_t ex2h2(float lo, float hi) {
    uint32_t p;
    asm("cvt.rn.f16x2.f32 %0, %2, %1;" : "=r"(p) : "f"(lo), "f"(hi));
    asm("ex2.approx.f16x2 %0, %0;" : "+r"(p));
    return p;
}
__device__ __forceinline__ float ex2f(float x) {
    float r;
    asm("ex2.approx.f32 %0, %1;" : "=f"(r) : "f"(x));
    return r;
}
__device__ __forceinline__ void mma16b(float* c, const uint32_t* a, uint32_t b0, uint32_t b1) {
    asm volatile(
        "mma.sync.aligned.m16n8k16.row.col.f32.f16.f16.f32 "
        "{%0,%1,%2,%3}, {%4,%5,%6,%7}, {%8,%9}, {%0,%1,%2,%3};"
        : "+f"(c[0]), "+f"(c[1]), "+f"(c[2]), "+f"(c[3])
        : "r"(a[0]), "r"(a[1]), "r"(a[2]), "r"(a[3]), "r"(b0), "r"(b1));
}
__device__ __forceinline__ void ldsm4(uint32_t* r, uint32_t addr) {
    asm volatile("ldmatrix.sync.aligned.m8n8.x4.shared.b16 {%0,%1,%2,%3}, [%4];"
                 : "=r"(r[0]), "=r"(r[1]), "=r"(r[2]), "=r"(r[3]) : "r"(addr));
}
__device__ __forceinline__ void ldsm4t(uint32_t* r, uint32_t addr) {
    asm volatile("ldmatrix.sync.aligned.m8n8.x4.trans.shared.b16 {%0,%1,%2,%3}, [%4];"
                 : "=r"(r[0]), "=r"(r[1]), "=r"(r[2]), "=r"(r[3]) : "r"(addr));
}
__device__ __forceinline__ uint32_t smem_u32(const void* p) {
    uint32_t a;
    asm("{ .reg .u64 t; cvta.to.shared.u64 t, %1; cvt.u32.u64 %0, t; }" : "=r"(a) : "l"(p));
    return a;
}
#define CPA16(dst, src) \
    asm volatile("cp.async.cg.shared.global [%0], [%1], 16;" ::"r"(dst), "l"(src) : "memory")
#define CPA_COMMIT() asm volatile("cp.async.commit_group;" ::: "memory")

// ================= fused flash attention (log2 softmax, fp16 output) =================
__global__ void __launch_bounds__(128, 2)
flash_attn(const __half* __restrict__ Qg, const __half* __restrict__ Kg,
           const __half* __restrict__ Vg, const float* __restrict__ maskg,
           __half* __restrict__ Og) {
    extern __shared__ uint32_t smu[];
    float* Ms = (float*)(smu + 18432);
    const uint32_t sbase = smem_u32(smu);

    const int bh = blockIdx.y;
    const int b = bh / 12, h = bh % 12;
    const __half* Q = Qg + (size_t)bh * 65536;
    const __half* K = Kg + (size_t)bh * 65536;
    const __half* V = Vg + (size_t)bh * 65536;
    const float* mask = maskg + b * 1024;
    __half* O = Og + (size_t)b * 1024 * 768 + h * 64;

    const int tid = threadIdx.x;
    const int wid = tid >> 5, lane = tid & 31;
    const int qr = lane >> 2, qc = lane & 3;
    const int m0row = blockIdx.x * 64 + wid * 16;

    const int nrow = (lane & 7) | ((lane >> 4) << 3);
    const int koff8 = ((lane >> 3) & 1) << 3;
    const int krow = (lane & 7) + ((lane >> 3) & 1) * 8;
    const int noff8 = ((lane >> 4) << 3);
    const uint32_t ONE2 = 0x3C003C00u;

    auto kv_load = [&](int c, int buf) {
        uint32_t dstK = sbase + buf * 36864;
        uint32_t dstV = dstK + 18432;
        const __half* Kc = K + ((size_t)(c << 7)) * 64;
        const __half* Vc = V + ((size_t)(c << 7)) * 64;
#pragma unroll
        for (int j = 0; j < 8; j++) {
            int idx = tid + (j << 7);
            int kv = idx >> 3, c4 = idx & 7;
            CPA16(dstK + kv * 144 + c4 * 16, Kc + (size_t)kv * 64 + c4 * 8);
            CPA16(dstV + kv * 144 + c4 * 16, Vc + (size_t)kv * 64 + c4 * 8);
        }
    };
#pragma unroll
    for (int j = 0; j < 2; j++) {
        int idx = tid + (j << 7);
        CPA16(smem_u32(Ms + idx * 4), mask + idx * 4);
    }
    kv_load(0, 0);
    CPA_COMMIT();
    kv_load(1, 1);
    CPA_COMMIT();

    uint32_t qf[4][4];
    {
        const float qs = 0.125f * LOG2E;
        const __half* Qr0 = Q + (size_t)(m0row + qr) * 64;
        const __half* Qr1 = Q + (size_t)(m0row + qr + 8) * 64;
#pragma unroll
        for (int kd = 0; kd < 4; kd++) {
            float2 t0 = __half22float2(*(const __half2*)(Qr0 + kd * 16 + 2 * qc));
            float2 t1 = __half22float2(*(const __half2*)(Qr1 + kd * 16 + 2 * qc));
            float2 t2 = __half22float2(*(const __half2*)(Qr0 + kd * 16 + 2 * qc + 8));
            float2 t3 = __half22float2(*(const __half2*)(Qr1 + kd * 16 + 2 * qc + 8));
            qf[kd][0] = h2u(t0.x * qs, t0.y * qs);
            qf[kd][1] = h2u(t1.x * qs, t1.y * qs);
            qf[kd][2] = h2u(t2.x * qs, t2.y * qs);
            qf[kd][3] = h2u(t3.x * qs, t3.y * qs);
        }
    }

    float oacc[8][4];
#pragma unroll
    for (int i = 0; i < 8; i++)
#pragma unroll
        for (int j = 0; j < 4; j++) oacc[i][j] = 0.0f;
    float lacc[4] = {0.0f, 0.0f, 0.0f, 0.0f};
    float mrow0 = -INFINITY, mrow1 = -INFINITY;

    for (int c = 0; c < 8; c++) {
        const int buf = c & 1;
        const uint32_t ksb = sbase + buf * 36864;
        const uint32_t vsb = ksb + 18432;
        const int kvb = c << 7;

        if (c < 7) asm volatile("cp.async.wait_group 1;" ::: "memory");
        else       asm volatile("cp.async.wait_group 0;" ::: "memory");
        __syncthreads();

        float sacc[16][4];
#pragma unroll
        for (int nt = 0; nt < 16; nt++)
            sacc[nt][0] = sacc[nt][1] = sacc[nt][2] = sacc[nt][3] = 0.0f;
#pragma unroll
        for (int ntp = 0; ntp < 8; ntp++) {
            const uint32_t rowb = ksb + (uint32_t)(ntp * 16 + nrow) * 144;
#pragma unroll
            for (int kd = 0; kd < 4; kd++) {
                uint32_t bb[4];
                ldsm4(bb, rowb + (uint32_t)(kd * 16 + koff8) * 2);
                mma16b(sacc[2 * ntp], qf[kd], bb[0], bb[1]);
                mma16b(sacc[2 * ntp + 1], qf[kd], bb[2], bb[3]);
            }
        }

        float cm0 = -INFINITY, cm1 = -INFINITY;
#pragma unroll
        for (int nt = 0; nt < 16; nt++) {
            float mk0 = Ms[kvb + nt * 8 + 2 * qc] * LOG2E;
            float mk1 = Ms[kvb + nt * 8 + 2 * qc + 1] * LOG2E;
            sacc[nt][0] += mk0; sacc[nt][1] += mk1;
            sacc[nt][2] += mk0; sacc[nt][3] += mk1;
            cm0 = fmaxf(cm0, fmaxf(sacc[nt][0], sacc[nt][1]));
            cm1 = fmaxf(cm1, fmaxf(sacc[nt][2], sacc[nt][3]));
        }
        cm0 = fmaxf(cm0, __shfl_xor_sync(0xffffffffu, cm0, 1));
        cm0 = fmaxf(cm0, __shfl_xor_sync(0xffffffffu, cm0, 2));
        cm1 = fmaxf(cm1, __shfl_xor_sync(0xffffffffu, cm1, 1));
        cm1 = fmaxf(cm1, __shfl_xor_sync(0xffffffffu, cm1, 2));
        const float mn0 = fmaxf(mrow0, cm0), mn1 = fmaxf(mrow1, cm1);
        const float al0 = ex2f(mrow0 - mn0), al1 = ex2f(mrow1 - mn1);
        mrow0 = mn0; mrow1 = mn1;
#pragma unroll
        for (int i = 0; i < 8; i++) {
            oacc[i][0] *= al0; oacc[i][1] *= al0;
            oacc[i][2] *= al1; oacc[i][3] *= al1;
        }
        lacc[0] *= al0; lacc[1] *= al0; lacc[2] *= al1; lacc[3] *= al1;

#pragma unroll
        for (int kt2 = 0; kt2 < 8; kt2++) {
            uint32_t af[4];
            af[0] = ex2h2(sacc[2 * kt2][0] - mn0, sacc[2 * kt2][1] - mn0);
            af[1] = ex2h2(sacc[2 * kt2][2] - mn1, sacc[2 * kt2][3] - mn1);
            af[2] = ex2h2(sacc[2 * kt2 + 1][0] - mn0, sacc[2 * kt2 + 1][1] - mn0);
            af[3] = ex2h2(sacc[2 * kt2 + 1][2] - mn1, sacc[2 * kt2 + 1][3] - mn1);
            mma16b(lacc, af, ONE2, ONE2);
            const uint32_t rowb = vsb + (uint32_t)(kt2 * 16 + krow) * 144;
#pragma unroll
            for (int dtp = 0; dtp < 4; dtp++) {
                uint32_t bb[4];
                ldsm4t(bb, rowb + (uint32_t)(dtp * 16 + noff8) * 2);
                mma16b(oacc[2 * dtp], af, bb[0], bb[1]);
                mma16b(oacc[2 * dtp + 1], af, bb[2], bb[3]);
            }
        }
        __syncthreads();
        if (c + 2 < 8) { kv_load(c + 2, buf); CPA_COMMIT(); }
    }

    const float il0 = 1.0f / lacc[0], il1 = 1.0f / lacc[2];
    const int r0 = m0row + qr, r1 = m0row + qr + 8;
#pragma unroll
    for (int nt2 = 0; nt2 < 8; nt2++) {
        const int col = nt2 * 8 + 2 * qc;
        *(uint32_t*)(O + (size_t)r0 * 768 + col) =
            h2u(oacc[nt2][0] * il0, oacc[nt2][1] * il0);
        *(uint32_t*)(O + (size_t)r1 * 768 + col) =
            h2u(oacc[nt2][2] * il1, oacc[nt2][3] * il1);
    }
}

// ---------------- fp16 mma GEMM; B fp16 cp.async; A fp32(reg) or fp16(cp.async) ----------------
// mode bits: 1 = gelu, 2 = fp16 output. z = (i1*D2 + i2)*D3 + i3. Strides in elements.
template <int BN, int NSUM, int AH = 0>
__global__ void __launch_bounds__(256, 2)
gemm_mma(const float* __restrict__ A, const __half* __restrict__ Bh, void* __restrict__ Cv,
         const float* __restrict__ bias, const float* __restrict__ res,
         int lda, int ldb, int ldc, int ldres, int K, float scale, int mode,
         int D2, int D3, long long sum_str,
         long long sA1, long long sA2, long long sA3,
         long long sB1, long long sB2, long long sB3,
         long long sC1, long long sC2, long long sC3,
         long long sb1, long long sb2, long long sb3) {
    constexpr int BM = 128, NT = 256, WN = BN / 4, NTILES = WN / 8, NPAIR = NTILES / 2;
    constexpr int AROW = 20;
    constexpr int BROW = BN / 2 + 4;
    constexpr int BCH = BN / 8;
    constexpr int LB = (32 * BCH) / NT > 0 ? (32 * BCH) / NT : 1;

    __shared__ uint32_t As32[2][BM * AROW];
    __shared__ uint32_t Bs32[2][32 * BROW];

    const int z = blockIdx.z;
    const int i1 = z / (D2 * D3);
    const int rem = z % (D2 * D3);
    const int i2 = rem / D3, i3 = rem % D3;
    const __half* Ah = (const __half*)A;
    if (AH) Ah += i1 * sA1 + i2 * sA2 + i3 * sA3;
    else A += i1 * sA1 + i2 * sA2 + i3 * sA3;
    Bh += i1 * sB1 + i2 * sB2 + i3 * sB3;
    const long long coff = i1 * sC1 + i2 * sC2 + i3 * sC3;
    const long long boff = i1 * sb1 + i2 * sb2 + i3 * sb3;

    const int x0 = blockIdx.x * BN, y0 = blockIdx.y * BM;
    const int tid = threadIdx.x;
    const int wid = tid >> 5, lane = tid & 31;
    const int wm0 = (wid >> 2) * 64;
    const int wn0 = (wid & 3) * WN;
    const int qr = lane >> 2, qc = lane & 3;

    const uint32_t aBase = smem_u32(As32);
    const uint32_t bBase = smem_u32(Bs32);
    const int arow_l = lane & 15, akoff = ((lane >> 4) << 3);
    const int bkrow = (lane & 7) + ((lane >> 3) & 1) * 8, bnoff = ((lane >> 4) << 3);

    float4 ra[4];

    auto cpa = [&](int k0, int buf) {
        const uint32_t bB = bBase + buf * (32 * BROW * 4);
#pragma unroll
        for (int i = 0; i < LB; i++) {
            int f = tid + i * NT;
            int k = f / BCH, c8 = f % BCH;
            CPA16(bB + (uint32_t)(k * BROW * 4 + c8 * 16),
                  Bh + (size_t)(k0 + k) * ldb + x0 + c8 * 8);
        }
        if (AH) {
            const uint32_t aB = aBase + buf * (BM * AROW * 4);
#pragma unroll
            for (int i = 0; i < 2; i++) {
                int f = tid + i * NT;
                int m = f >> 2, c4 = f & 3;
                CPA16(aB + (uint32_t)(m * AROW * 4 + c4 * 16),
                      Ah + (size_t)(y0 + m) * lda + k0 + c4 * 8);
            }
        }
    };
    auto ldgA = [&](int k0) {
        if (!AH) {
#pragma unroll
            for (int i = 0; i < 4; i++) {
                int f = tid + i * NT;
                int m = f >> 3, kq = f & 7;
                const float* ap = A + (size_t)(y0 + m) * lda + k0 + kq * 4;
                float4 v = *(const float4*)ap;
#pragma unroll
                for (int s = 1; s < NSUM; s++) {
                    float4 w = *(const float4*)(ap + (size_t)s * sum_str);
                    v.x += w.x; v.y += w.y; v.z += w.z; v.w += w.w;
                }
                ra[i] = v;
            }
        }
    };
    auto stsA = [&](int buf) {
        if (!AH) {
#pragma unroll
            for (int i = 0; i < 4; i++) {
                int f = tid + i * NT;
                int m = f >> 3, kq = f & 7;
                As32[buf][m * AROW + 2 * kq] = h2u(ra[i].x, ra[i].y);
                As32[buf][m * AROW + 2 * kq + 1] = h2u(ra[i].z, ra[i].w);
            }
        }
    };

    float acc[4][NTILES][4];
#pragma unroll
    for (int i = 0; i < 4; i++)
#pragma unroll
        for (int j = 0; j < NTILES; j++)
#pragma unroll
            for (int l = 0; l < 4; l++) acc[i][j][l] = 0.0f;

    ldgA(0);
    cpa(0, 0);
    CPA_COMMIT();
    stsA(0);
    asm volatile("cp.async.wait_group 0;" ::: "memory");
    __syncthreads();

    const int nb = K >> 5;
    for (int kb = 0; kb < nb; kb++) {
        const int cur = kb & 1;
        if (kb + 1 < nb) {
            ldgA((kb + 1) << 5);
            cpa((kb + 1) << 5, cur ^ 1);
            CPA_COMMIT();
        }
        const uint32_t aB = aBase + cur * (BM * AROW * 4);
        const uint32_t bB = bBase + cur * (32 * BROW * 4);
#pragma unroll
        for (int kk = 0; kk < 2; kk++) {
            uint32_t af[4][4], bb[NPAIR][4];
#pragma unroll
            for (int mt = 0; mt < 4; mt++)
                ldsm4(af[mt], aB + (uint32_t)(wm0 + mt * 16 + arow_l) * 80 +
                                  (uint32_t)(kk * 16 + akoff) * 2);
#pragma unroll
            for (int p = 0; p < NPAIR; p++)
                ldsm4t(bb[p], bB + (uint32_t)(kk * 16 + bkrow) * (BROW * 4) +
                                  (uint32_t)(wn0 + p * 16 + bnoff) * 2);
#pragma unroll
            for (int mt = 0; mt < 4; mt++)
#pragma unroll
                for (int p = 0; p < NPAIR; p++) {
                    mma16b(acc[mt][2 * p], af[mt], bb[p][0], bb[p][1]);
                    mma16b(acc[mt][2 * p + 1], af[mt], bb[p][2], bb[p][3]);
                }
        }
        if (kb + 1 < nb) {
            stsA(cur ^ 1);
            asm volatile("cp.async.wait_group 0;" ::: "memory");
        }
        __syncthreads();
    }

    float* Cf = (float*)Cv + coff;
    __half* Ch = (__half*)Cv + coff;
#pragma unroll
    for (int mt = 0; mt < 4; mt++) {
#pragma unroll
        for (int nt = 0; nt < NTILES; nt++) {
            const int n = x0 + wn0 + nt * 8 + qc * 2;
#pragma unroll
            for (int half_ = 0; half_ < 2; half_++) {
                const int m = y0 + wm0 + mt * 16 + qr + half_ * 8;
                float v0 = acc[mt][nt][half_ * 2 + 0] * scale;
                float v1 = acc[mt][nt][half_ * 2 + 1] * scale;
                if (bias) { v0 += bias[boff + n]; v1 += bias[boff + n + 1]; }
                if (res) {
                    v0 += res[(size_t)m * ldres + n];
                    v1 += res[(size_t)m * ldres + n + 1];
                }
                if (mode & 1) { v0 = gelu_exact(v0); v1 = gelu_exact(v1); }
                if (mode & 2) {
                    *(uint32_t*)(Ch + (size_t)m * ldc + n) = h2u(v0, v1);
                } else {
                    *(float2*)(Cf + (size_t)m * ldc + n) = make_float2(v0, v1);
                }
            }
        }
    }
}

// ---------------- packing: all weights to fp16 ----------------
__global__ void pack_all(const float* __restrict__ Pq, const float* __restrict__ Pk,
                         const float* __restrict__ Pv,
                         const float* __restrict__ Vq, const float* __restrict__ Vk,
                         const float* __restrict__ Vv,
                         const float* __restrict__ bq, const float* __restrict__ bk,
                         const float* __restrict__ bv,
                         const float* __restrict__ Uo, const float* __restrict__ Vo,
                         const float* __restrict__ U1, const float* __restrict__ V1,
                         const float* __restrict__ U2, const float* __restrict__ V2,
                         __half* __restrict__ WH, float* __restrict__ VB) {
    int idx = blockIdx.x * blockDim.x + threadIdx.x;
    if (idx < 884736) {
        int q = idx / (768 * 384);
        int r2 = idx % (768 * 384);
        int k = r2 / 384, n = r2 % 384;
        const float* P = (q == 0) ? Pq : ((q == 1) ? Pk : Pv);
        WH[idx] = __float2half_rn(P[((size_t)(n >> 5) * 768 + k) * 32 + (n & 31)]);
    } else if (idx < 958464) {
        int e = idx - 884736;
        int q = e / 24576, r = e % 24576;
        const float* S = (q == 0) ? Vq : ((q == 1) ? Vk : Vv);
        WH[idx] = __float2half_rn(S[r]);
    } else if (idx < 1253376) {
        WH[idx] = __float2half_rn(Uo[idx - 958464]);
    } else if (idx < 1548288) {
        WH[idx] = __float2half_rn(Vo[idx - 1253376]);
    } else if (idx < 1843200) {
        WH[idx] = __float2half_rn(U1[idx - 1548288]);
    } else if (idx < 3022848) {
        WH[idx] = __float2half_rn(V1[idx - 1843200]);
    } else if (idx < 4202496) {
        WH[idx] = __float2half_rn(U2[idx - 3022848]);
    } else if (idx < 4497408) {
        WH[idx] = __float2half_rn(V2[idx - 4202496]);
    } else if (idx < 4497408 + 2304) {
        int e = idx - 4497408;
        int q = e / 768, r = e % 768;
        const float* S = (q == 0) ? bq : ((q == 1) ? bk : bv);
        VB[e] = S[r];
    }
}

// ---------------- LayerNorm (single pass) ----------------
__global__ void ln_kernel(const float* __restrict__ in, float* __restrict__ out,
                          const float* __restrict__ g, const float* __restrict__ bb) {
    __shared__ float rs_[8], rss_[8];
    const float* xr = in + (size_t)blockIdx.x * 768;
    float* yr = out + (size_t)blockIdx.x * 768;
    const int tid = threadIdx.x;
    float v[3];
    float s = 0.0f, ss = 0.0f;
#pragma unroll
    for (int i = 0; i < 3; i++) {
        v[i] = xr[tid + i * 256];
        s += v[i];
        ss += v[i] * v[i];
    }
#pragma unroll
    for (int o = 16; o; o >>= 1) {
        s += __shfl_xor_sync(0xffffffffu, s, o);
        ss += __shfl_xor_sync(0xffffffffu, ss, o);
    }
    if ((tid & 31) == 0) { rs_[tid >> 5] = s; rss_[tid >> 5] = ss; }
    __syncthreads();
    s = 0.0f; ss = 0.0f;
#pragma unroll
    for (int w = 0; w < 8; w++) { s += rs_[w]; ss += rss_[w]; }
    const float mu = s * (1.0f / 768.0f);
    const float var = fmaxf(ss * (1.0f / 768.0f) - mu * mu, 0.0f);
    const float rstd = rsqrtf(var + 1e-12f);
#pragma unroll
    for (int i = 0; i < 3; i++) {
        int c = tid + i * 256;
        yr[c] = (v[i] - mu) * rstd * g[c] + bb[c];
    }
}

extern "C" void kernel_launch(void* const* d_in, const int* in_sizes, int n_in,
                              void* d_out, int out_size) {
    const float* x    = (const float*)d_in[0];
    const float* mask = (const float*)d_in[1];
    const float* Pq   = (const float*)d_in[2];
    const float* Vq   = (const float*)d_in[3];
    const float* bq   = (const float*)d_in[4];
    const float* Pk   = (const float*)d_in[5];
    const float* Vk   = (const float*)d_in[6];
    const float* bk   = (const float*)d_in[7];
    const float* Pv   = (const float*)d_in[8];
    const float* Vv   = (const float*)d_in[9];
    const float* bv   = (const float*)d_in[10];
    const float* Uo   = (const float*)d_in[11];
    const float* Vo   = (const float*)d_in[12];
    const float* bo   = (const float*)d_in[13];
    const float* U1   = (const float*)d_in[14];
    const float* V1   = (const float*)d_in[15];
    const float* b1   = (const float*)d_in[16];
    const float* U2   = (const float*)d_in[17];
    const float* V2   = (const float*)d_in[18];
    const float* b2   = (const float*)d_in[19];
    const float* ln1g = (const float*)d_in[20];
    const float* ln1b = (const float*)d_in[21];
    const float* ln2g = (const float*)d_in[22];
    const float* ln2b = (const float*)d_in[23];
    float* out = (float*)d_out;

    float *vb_p, *tmp_p, *x1_p, *y_p;
    __half *wh_p, *wod_p, *th_p, *qkv_p, *at2_p, *hdnh_p;
    cudaGetSymbolAddress((void**)&wh_p,   g_wh);
    cudaGetSymbolAddress((void**)&wod_p,  g_wod);
    cudaGetSymbolAddress((void**)&vb_p,   g_vb);
    cudaGetSymbolAddress((void**)&th_p,   g_th);
    cudaGetSymbolAddress((void**)&qkv_p,  g_qkvh);
    cudaGetSymbolAddress((void**)&at2_p,  g_at2h);
    cudaGetSymbolAddress((void**)&tmp_p,  g_tmp);
    cudaGetSymbolAddress((void**)&x1_p,   g_x1);
    cudaGetSymbolAddress((void**)&y_p,    g_y);
    cudaGetSymbolAddress((void**)&hdnh_p, g_hdnh);

    const long long T_QKV = 3145728, Q_QKV = 6291456, W_SZ = 294912;
    const long long PART = 3145728;
    const long long OFF_VW = 884736, OFF_UO = 958464, OFF_VO = 1253376,
                    OFF_U1 = 1548288, OFF_V1 = 1843200, OFF_U2 = 3022848,
                    OFF_V2 = 4202496;
    const int FL_SMEM = 77824;
    cudaFuncSetAttribute(flash_attn, cudaFuncAttributeMaxDynamicSharedMemorySize, FL_SMEM);

    // 0) pack all weights to fp16
    const int NPACK = 4497408 + 2304;
    pack_all<<<(NPACK + 255) / 256, 256>>>(Pq, Pk, Pv, Vq, Vk, Vv, bq, bk, bv,
                                           Uo, Vo, U1, V1, U2, V2, wh_p, vb_p);

    // 0b) Wod = Uo @ Vo -> fp16 [768,768]
    gemm_mma<128, 1, 1><<<dim3(6, 6, 1), 256>>>(
        (const float*)(wh_p + OFF_UO), wh_p + OFF_VO, wod_p, nullptr, nullptr,
        384, 768, 768, 0, 384, 1.0f, 2, 1, 1, 0LL,
        0, 0, 0, 0, 0, 0, 0, 0, 0, 0, 0, 0);

    // 1) t = x @ W -> fp16  (fp32 A path; z over qkv)
    gemm_mma<128, 1><<<dim3(3, 64, 3), 256>>>(
        x, wh_p, th_p, nullptr, nullptr,
        768, 384, 384, 0, 768, 1.0f, 2, 1, 1, 0LL,
        0LL, 0LL, 0LL, W_SZ, 0LL, 0LL, T_QKV, 0LL, 0LL, 0LL, 0LL, 0LL);

    // 2) Q/K/V = t(fp16) @ Vqkv + b -> fp16. z=(q,b,h), K=32
    gemm_mma<64, 1, 1><<<dim3(1, 8, 288), 256>>>(
        (const float*)th_p, wh_p + OFF_VW, qkv_p, vb_p, nullptr,
        384, 64, 64, 0, 32, 1.0f, 2, 8, 12, 0LL,
        T_QKV, 393216LL, 32LL,
        24576LL, 0LL, 2048LL,
        Q_QKV, 786432LL, 65536LL,
        768LL, 0LL, 64LL);

    // 3) fused attention -> at2 (fp16)
    flash_attn<<<dim3(16, 96), 128, FL_SMEM>>>(
        qkv_p, qkv_p + Q_QKV, qkv_p + 2 * Q_QKV, mask, at2_p);

    // 4) x1pre = attn @ Wod + bo + x   (fused Uo@Vo, K=768, fp16 A)
    gemm_mma<128, 1, 1><<<dim3(6, 64, 1), 256>>>(
        (const float*)at2_p, wod_p, y_p, bo, x,
        768, 768, 768, 768, 768, 1.0f, 0, 1, 1, 0LL,
        0, 0, 0, 0, 0, 0, 0, 0, 0, 0, 0, 0);

    // 5) LN1
    ln_kernel<<<8192, 256>>>(y_p, x1_p, ln1g, ln1b);

    // 6) mid partials = x1 @ U1  (split-K x2, fp32 A path)
    gemm_mma<128, 1><<<dim3(3, 64, 2), 256>>>(
        x1_p, wh_p + OFF_U1, tmp_p, nullptr, nullptr,
        768, 384, 384, 0, 384, 1.0f, 0, 1, 2, 0LL,
        0LL, 0LL, 384LL, 0LL, 0LL, 147456LL, 0LL, 0LL, PART, 0, 0, 0);

    // 7) hdn = gelu(sum(mid) @ V1 + b1) -> fp16
    gemm_mma<128, 2><<<dim3(24, 64, 1), 256>>>(
        tmp_p, wh_p + OFF_V1, hdnh_p, b1, nullptr,
        384, 3072, 3072, 0, 384, 1.0f, 3, 1, 1, PART,
        0, 0, 0, 0, 0, 0, 0, 0, 0, 0, 0, 0);

    // 8) h2 partials = hdn(fp16) @ U2  (split-K x4)
    gemm_mma<128, 1, 1><<<dim3(3, 64, 4), 256>>>(
        (const float*)hdnh_p, wh_p + OFF_U2, tmp_p, nullptr, nullptr,
        3072, 384, 384, 0, 768, 1.0f, 0, 1, 4, 0LL,
        0LL, 0LL, 768LL, 0LL, 0LL, 294912LL, 0LL, 0LL, PART, 0, 0, 0);

    // 9) ypre = sum(h2) @ V2 + b2 + x1
    gemm_mma<128, 4><<<dim3(6, 64, 1), 256>>>(
        tmp_p, wh_p + OFF_V2, y_p, b2, x1_p,
        384, 768, 768, 768, 384, 1.0f, 0, 1, 1, PART,
        0, 0, 0, 0, 0, 0, 0, 0, 0, 0, 0, 0);

    // 10) LN2 -> out
    ln_kernel<<<8192, 256>>>(y_p, out, ln2g, ln2b);
}